// round 2
// baseline (speedup 1.0000x reference)
#include <cuda_runtime.h>
#include <math.h>

#define BQ     2048
#define MKEYS  131072
#define EDIM   256
#define KDIM   128
#define VDIM   256
#define ODIM   256
#define H1     512
#define AH     128
#define IH     512
#define CDIM   (EDIM + VDIM)   // 512
#define NCHUNK (MKEYS / 128)   // 1024
#define PADW   132             // smem row pitch (floats)
#define NEG_BIG (-1e9f)

// ---------------- scratch (static device globals; no allocation) ----------------
__device__ float g_hidden[BQ * H1];          // 4 MB
__device__ float g_qn[BQ * KDIM];            // 1 MB
__device__ float g_invn[MKEYS];              // 0.5 MB
__device__ float g_pval[BQ * NCHUNK * 3];    // 25 MB
__device__ int   g_pidx[BQ * NCHUNK * 3];    // 25 MB
__device__ int   g_topidx[BQ * 3];
__device__ int   g_hitflag[BQ * 3];
__device__ int   g_anyhit[BQ];
__device__ float g_comb[BQ * CDIM];          // 4 MB
__device__ float g_g1[BQ * IH];              // 4 MB

// ---------------- f32x2 helpers (Blackwell packed fp32) ----------------
typedef unsigned long long ull;

__device__ __forceinline__ ull pack2(float x, float y) {
    ull r;
    asm("mov.b64 %0, {%1, %2};" : "=l"(r) : "f"(x), "f"(y));
    return r;
}
__device__ __forceinline__ void fma2(ull& d, ull a, ull b) {
    asm("fma.rn.f32x2 %0, %1, %2, %0;" : "+l"(d) : "l"(a), "l"(b));
}
__device__ __forceinline__ float2 unpack2(ull v) {
    float2 f;
    asm("mov.b64 {%0, %1}, %2;" : "=f"(f.x), "=f"(f.y) : "l"(v));
    return f;
}

// ---------------- K1: hidden = relu(state @ k_w1 + k_b1) ----------------
__global__ void k1_hidden(const float* __restrict__ S, const float* __restrict__ W,
                          const float* __restrict__ b) {
    __shared__ float xs[16][EDIM];
    int r0 = blockIdx.x * 16;
    int tid = threadIdx.x;
    for (int i = tid; i < 16 * EDIM; i += 256) {
        int r = i >> 8, c = i & 255;
        xs[r][c] = S[(r0 + r) * EDIM + c];
    }
    __syncthreads();
    for (int j = tid; j < H1; j += 256) {
        float acc[16];
        float bj = b[j];
#pragma unroll
        for (int r = 0; r < 16; r++) acc[r] = bj;
        for (int k = 0; k < EDIM; k++) {
            float w = W[k * H1 + j];
#pragma unroll
            for (int r = 0; r < 16; r++) acc[r] = fmaf(xs[r][k], w, acc[r]);
        }
#pragma unroll
        for (int r = 0; r < 16; r++) g_hidden[(r0 + r) * H1 + j] = fmaxf(acc[r], 0.f);
    }
}

// ---------------- K2: query = hidden @ k_w2 + k_b2, then row-normalize -> g_qn ----------------
__global__ void k2_query(const float* __restrict__ W, const float* __restrict__ b) {
    __shared__ float xs[16][H1];
    __shared__ float qs[16][KDIM];
    __shared__ float sinv[16];
    int r0 = blockIdx.x * 16;
    int tid = threadIdx.x;  // 128 threads
    for (int i = tid; i < 16 * H1; i += 128) {
        int r = i >> 9, c = i & 511;
        xs[r][c] = g_hidden[(r0 + r) * H1 + c];
    }
    __syncthreads();
    int j = tid;
    float acc[16];
    float bj = b[j];
#pragma unroll
    for (int r = 0; r < 16; r++) acc[r] = bj;
    for (int k = 0; k < H1; k++) {
        float w = W[k * KDIM + j];
#pragma unroll
        for (int r = 0; r < 16; r++) acc[r] = fmaf(xs[r][k], w, acc[r]);
    }
#pragma unroll
    for (int r = 0; r < 16; r++) qs[r][j] = acc[r];
    __syncthreads();
    if (tid < 16) {
        float s = 0.f;
        for (int c = 0; c < KDIM; c++) { float v = qs[tid][c]; s += v * v; }
        sinv[tid] = 1.f / fmaxf(sqrtf(s), 1e-8f);
    }
    __syncthreads();
    for (int i = tid; i < 16 * KDIM; i += 128) {
        int r = i >> 7, c = i & 127;
        g_qn[(r0 + r) * KDIM + c] = qs[r][c] * sinv[r];
    }
}

// ---------------- K3: per-key inverse norms ----------------
__global__ void k3_invn(const float* __restrict__ keys) {
    int warp = threadIdx.x >> 5, lane = threadIdx.x & 31;
    int row = blockIdx.x * 8 + warp;
    const float4* k4p = (const float4*)keys;
    float4 v = k4p[(size_t)row * 32 + lane];
    float s = v.x * v.x + v.y * v.y + v.z * v.z + v.w * v.w;
#pragma unroll
    for (int o = 16; o > 0; o >>= 1) s += __shfl_xor_sync(0xffffffffu, s, o);
    if (lane == 0) g_invn[row] = 1.f / fmaxf(sqrtf(s), 1e-8f);
}

// ---------------- K4: fused sims GEMM (fp32x2) + per-tile top-3 ----------------
__global__ void __launch_bounds__(256, 1)
k4_sims(const float* __restrict__ keys) {
    extern __shared__ float sm[];
    float* As = sm;                 // [128][PADW]  qn tile, [k][r]
    float* Bs = sm + 128 * PADW;    // [128][PADW]  key tile, [k][c]
    int row0 = blockIdx.y * 128;
    int key0 = blockIdx.x * 128;
    int tid = threadIdx.x;

    const float4* q4 = (const float4*)g_qn;
#pragma unroll
    for (int i = 0; i < 16; i++) {
        int idx = i * 256 + tid;
        int r = idx >> 5, k4 = idx & 31;
        float4 v = q4[(row0 + r) * 32 + k4];
        As[(k4 * 4 + 0) * PADW + r] = v.x;
        As[(k4 * 4 + 1) * PADW + r] = v.y;
        As[(k4 * 4 + 2) * PADW + r] = v.z;
        As[(k4 * 4 + 3) * PADW + r] = v.w;
    }
    const float4* kp4 = (const float4*)keys;
#pragma unroll
    for (int i = 0; i < 16; i++) {
        int idx = i * 256 + tid;
        int c = idx >> 5, k4 = idx & 31;
        float4 v = kp4[(size_t)(key0 + c) * 32 + k4];
        Bs[(k4 * 4 + 0) * PADW + c] = v.x;
        Bs[(k4 * 4 + 1) * PADW + c] = v.y;
        Bs[(k4 * 4 + 2) * PADW + c] = v.z;
        Bs[(k4 * 4 + 3) * PADW + c] = v.w;
    }
    __syncthreads();

    int tx = tid & 15, ty = tid >> 4;
    ull acc[8][4];
#pragma unroll
    for (int i = 0; i < 8; i++)
#pragma unroll
        for (int j = 0; j < 4; j++) acc[i][j] = 0ull;

#pragma unroll 4
    for (int k = 0; k < 128; k++) {
        const float4* ap = (const float4*)(As + k * PADW + ty * 8);
        float4 a0 = ap[0], a1 = ap[1];
        const float4* bp = (const float4*)(Bs + k * PADW + tx * 8);
        float4 b0 = bp[0], b1 = bp[1];
        ull bb[4] = { pack2(b0.x, b0.y), pack2(b0.z, b0.w),
                      pack2(b1.x, b1.y), pack2(b1.z, b1.w) };
        ull av[8] = { pack2(a0.x, a0.x), pack2(a0.y, a0.y), pack2(a0.z, a0.z), pack2(a0.w, a0.w),
                      pack2(a1.x, a1.x), pack2(a1.y, a1.y), pack2(a1.z, a1.z), pack2(a1.w, a1.w) };
#pragma unroll
        for (int i = 0; i < 8; i++)
#pragma unroll
            for (int j = 0; j < 4; j++) fma2(acc[i][j], av[i], bb[j]);
    }

    // scale by key inverse norms, stage sims tile in smem (reuse As)
    __syncthreads();
    float* Sm = As;  // [128][PADW], [r][c]
    float invn[8];
#pragma unroll
    for (int j = 0; j < 8; j++) invn[j] = g_invn[key0 + tx * 8 + j];
#pragma unroll
    for (int i = 0; i < 8; i++) {
        int r = ty * 8 + i;
#pragma unroll
        for (int j = 0; j < 4; j++) {
            float2 v = unpack2(acc[i][j]);
            Sm[r * PADW + tx * 8 + 2 * j]     = v.x * invn[2 * j];
            Sm[r * PADW + tx * 8 + 2 * j + 1] = v.y * invn[2 * j + 1];
        }
    }
    __syncthreads();

    // per-row top-3 within this 128-key tile (strict > keeps lowest idx on ties)
    if (tid < 128) {
        int r = tid;
        float v0 = -3.402823466e38f, v1 = v0, v2 = v0;
        int i0 = 0, i1 = 0, i2 = 0;
        for (int c = 0; c < 128; c++) {
            float v = Sm[r * PADW + c];
            if (v > v0)      { v2 = v1; i2 = i1; v1 = v0; i1 = i0; v0 = v; i0 = c; }
            else if (v > v1) { v2 = v1; i2 = i1; v1 = v; i1 = c; }
            else if (v > v2) { v2 = v; i2 = c; }
        }
        int base = ((row0 + r) * NCHUNK + blockIdx.x) * 3;
        g_pval[base + 0] = v0; g_pidx[base + 0] = key0 + i0;
        g_pval[base + 1] = v1; g_pidx[base + 1] = key0 + i1;
        g_pval[base + 2] = v2; g_pidx[base + 2] = key0 + i2;
    }
}

// ---------------- K5: merge per-chunk top-3 -> global top-3 per row ----------------
__device__ __forceinline__ bool better(float v, int i, float V, int I) {
    return (v > V) || (v == V && (unsigned)i < (unsigned)I);
}

__global__ void k5_merge() {
    int row = blockIdx.x;
    int tid = threadIdx.x;  // 128
    __shared__ float sv[128 * 3];
    __shared__ int   si[128 * 3];
    float v0 = -3.402823466e38f, v1 = v0, v2 = v0;
    int i0 = 0x7fffffff, i1 = 0x7fffffff, i2 = 0x7fffffff;
    for (int ci = tid; ci < NCHUNK; ci += 128) {
        int base = (row * NCHUNK + ci) * 3;
#pragma unroll
        for (int t = 0; t < 3; t++) {
            float v = g_pval[base + t];
            int   id = g_pidx[base + t];
            if (better(v, id, v0, i0))      { v2 = v1; i2 = i1; v1 = v0; i1 = i0; v0 = v; i0 = id; }
            else if (better(v, id, v1, i1)) { v2 = v1; i2 = i1; v1 = v; i1 = id; }
            else if (better(v, id, v2, i2)) { v2 = v; i2 = id; }
        }
    }
    sv[tid * 3 + 0] = v0; si[tid * 3 + 0] = i0;
    sv[tid * 3 + 1] = v1; si[tid * 3 + 1] = i1;
    sv[tid * 3 + 2] = v2; si[tid * 3 + 2] = i2;
    __syncthreads();
    if (tid == 0) {
        float V0 = -3.402823466e38f, V1 = V0, V2 = V0;
        int I0 = 0x7fffffff, I1 = 0x7fffffff, I2 = 0x7fffffff;
        for (int n = 0; n < 128 * 3; n++) {
            float v = sv[n]; int id = si[n];
            if (better(v, id, V0, I0))      { V2 = V1; I2 = I1; V1 = V0; I1 = I0; V0 = v; I0 = id; }
            else if (better(v, id, V1, I1)) { V2 = V1; I2 = I1; V1 = v; I1 = id; }
            else if (better(v, id, V2, I2)) { V2 = v; I2 = id; }
        }
        g_topidx[row * 3 + 0] = I0;
        g_topidx[row * 3 + 1] = I1;
        g_topidx[row * 3 + 2] = I2;
        int h0 = (V0 >= 0.0f), h1 = (V1 >= 0.0f), h2 = (V2 >= 0.0f);
        g_hitflag[row * 3 + 0] = h0;
        g_hitflag[row * 3 + 1] = h1;
        g_hitflag[row * 3 + 2] = h2;
        g_anyhit[row] = h0 | h1 | h2;
    }
}

// ---------------- K6: attention over retrieved memories; build combined ----------------
__global__ void k6_attn(const float* __restrict__ S, const float* __restrict__ values,
                        const float* __restrict__ aw1, const float* __restrict__ ab1,
                        const float* __restrict__ aw2, const float* __restrict__ ab2) {
    __shared__ float xs[EDIM];
    __shared__ float vs[3][VDIM];
    __shared__ float red[3][AH];
    __shared__ float lg[3];
    __shared__ float attn[3];
    __shared__ int sidx[3];
    __shared__ int shit[3];
    int row = blockIdx.x, tid = threadIdx.x;  // 128 threads
    if (tid < 3) { sidx[tid] = g_topidx[row * 3 + tid]; shit[tid] = g_hitflag[row * 3 + tid]; }
    for (int i = tid; i < EDIM; i += AH) xs[i] = S[row * EDIM + i];
    __syncthreads();
    for (int i = tid; i < 3 * VDIM; i += AH) {
        int t = i / VDIM, d = i - t * VDIM;
        vs[t][d] = values[(size_t)sidx[t] * VDIM + d];
    }
    __syncthreads();
    int j = tid;
    float accc = ab1[j];
    for (int k = 0; k < EDIM; k++) accc = fmaf(xs[k], aw1[k * AH + j], accc);
    float w2 = aw2[j];
#pragma unroll
    for (int t = 0; t < 3; t++) {
        float a = accc;
        for (int k = 0; k < VDIM; k++) a = fmaf(vs[t][k], aw1[(EDIM + k) * AH + j], a);
        red[t][j] = tanhf(a) * w2;
    }
    __syncthreads();
    if (tid < 3) {
        float s = ab2[0];
        for (int i = 0; i < AH; i++) s += red[tid][i];
        lg[tid] = shit[tid] ? s : NEG_BIG;
    }
    __syncthreads();
    if (tid == 0) {
        float m = fmaxf(lg[0], fmaxf(lg[1], lg[2]));
        float e0 = expf(lg[0] - m), e1 = expf(lg[1] - m), e2 = expf(lg[2] - m);
        float inv = 1.f / (e0 + e1 + e2);
        attn[0] = e0 * inv; attn[1] = e1 * inv; attn[2] = e2 * inv;
    }
    __syncthreads();
    for (int d = tid; d < VDIM; d += AH) {
        float m = attn[0] * vs[0][d] + attn[1] * vs[1][d] + attn[2] * vs[2][d];
        g_comb[row * CDIM + EDIM + d] = m;
    }
    for (int d = tid; d < EDIM; d += AH) g_comb[row * CDIM + d] = xs[d];
}

// ---------------- K7: g1 = relu(combined @ i_w1 + i_b1) ----------------
__global__ void k7_int1(const float* __restrict__ W, const float* __restrict__ b) {
    __shared__ float xs[16][CDIM];
    int r0 = blockIdx.x * 16, tid = threadIdx.x;  // 256 threads
    for (int i = tid; i < 16 * CDIM; i += 256) {
        int r = i >> 9, c = i & 511;
        xs[r][c] = g_comb[(r0 + r) * CDIM + c];
    }
    __syncthreads();
    for (int j = tid; j < IH; j += 256) {
        float acc[16];
        float bj = b[j];
#pragma unroll
        for (int r = 0; r < 16; r++) acc[r] = bj;
        for (int k = 0; k < CDIM; k++) {
            float w = W[k * IH + j];
#pragma unroll
            for (int r = 0; r < 16; r++) acc[r] = fmaf(xs[r][k], w, acc[r]);
        }
#pragma unroll
        for (int r = 0; r < 16; r++) g_g1[(r0 + r) * IH + j] = fmaxf(acc[r], 0.f);
    }
}

// ---------------- K8: out = g1 @ i_w2 + i_b2 ----------------
__global__ void k8_int2(const float* __restrict__ W, const float* __restrict__ b,
                        float* __restrict__ out) {
    __shared__ float xs[16][IH];
    int r0 = blockIdx.x * 16, tid = threadIdx.x;  // 256 threads
    for (int i = tid; i < 16 * IH; i += 256) {
        int r = i >> 9, c = i & 511;
        xs[r][c] = g_g1[(r0 + r) * IH + c];
    }
    __syncthreads();
    int j = tid;  // ODIM == 256
    float acc[16];
    float bj = b[j];
#pragma unroll
    for (int r = 0; r < 16; r++) acc[r] = bj;
    for (int k = 0; k < IH; k++) {
        float w = W[k * ODIM + j];
#pragma unroll
        for (int r = 0; r < 16; r++) acc[r] = fmaf(xs[r][k], w, acc[r]);
    }
#pragma unroll
    for (int r = 0; r < 16; r++) out[(r0 + r) * ODIM + j] = acc[r];
}

// ---------------- K9: fallback path for rows with no hit (rare/never) ----------------
__global__ void k9_fallback(const float* __restrict__ S,
                            const float* __restrict__ fw1, const float* __restrict__ fb1,
                            const float* __restrict__ fw2, const float* __restrict__ fb2,
                            float* __restrict__ out) {
    int row = blockIdx.x;
    if (g_anyhit[row]) return;
    __shared__ float xs[EDIM];
    __shared__ float h[IH];
    int tid = threadIdx.x;  // 256
    for (int i = tid; i < EDIM; i += 256) xs[i] = S[row * EDIM + i];
    __syncthreads();
    for (int j = tid; j < IH; j += 256) {
        float a = fb1[j];
        for (int k = 0; k < EDIM; k++) a = fmaf(xs[k], fw1[k * IH + j], a);
        h[j] = fmaxf(a, 0.f);
    }
    __syncthreads();
    {
        int j = tid;
        float a = fb2[j];
        for (int k = 0; k < IH; k++) a = fmaf(h[k], fw2[k * ODIM + j], a);
        out[row * ODIM + j] = a;
    }
}

// ---------------- launch ----------------
extern "C" void kernel_launch(void* const* d_in, const int* in_sizes, int n_in,
                              void* d_out, int out_size) {
    const float* S    = (const float*)d_in[0];
    const float* keys = (const float*)d_in[1];
    const float* vals = (const float*)d_in[2];
    const float* kw1  = (const float*)d_in[3];
    const float* kb1  = (const float*)d_in[4];
    const float* kw2  = (const float*)d_in[5];
    const float* kb2  = (const float*)d_in[6];
    const float* aw1  = (const float*)d_in[7];
    const float* ab1  = (const float*)d_in[8];
    const float* aw2  = (const float*)d_in[9];
    const float* ab2  = (const float*)d_in[10];
    const float* iw1  = (const float*)d_in[11];
    const float* ib1  = (const float*)d_in[12];
    const float* iw2  = (const float*)d_in[13];
    const float* ib2  = (const float*)d_in[14];
    const float* fw1  = (const float*)d_in[15];
    const float* fb1  = (const float*)d_in[16];
    const float* fw2  = (const float*)d_in[17];
    const float* fb2  = (const float*)d_in[18];
    float* out = (float*)d_out;

    const int smem_k4 = 2 * 128 * PADW * sizeof(float);  // 135168 B
    cudaFuncSetAttribute(k4_sims, cudaFuncAttributeMaxDynamicSharedMemorySize, smem_k4);

    k3_invn<<<MKEYS / 8, 256>>>(keys);
    k1_hidden<<<BQ / 16, 256>>>(S, kw1, kb1);
    k2_query<<<BQ / 16, 128>>>(kw2, kb2);
    k4_sims<<<dim3(MKEYS / 128, BQ / 128), 256, smem_k4>>>(keys);
    k5_merge<<<BQ, 128>>>();
    k6_attn<<<BQ, 128>>>(S, vals, aw1, ab1, aw2, ab2);
    k7_int1<<<BQ / 16, 256>>>(iw1, ib1);
    k8_int2<<<BQ / 16, 256>>>(iw2, ib2, out);
    k9_fallback<<<BQ, 256>>>(S, fw1, fb1, fw2, fb2, out);
}

// round 4
// speedup vs baseline: 3.9663x; 3.9663x over previous
#include <cuda_runtime.h>
#include <cuda_bf16.h>
#include <math.h>
#include <float.h>
#include <stdint.h>

#define BQ     2048
#define MKEYS  131072
#define EDIM   256
#define KDIM   128
#define VDIM   256
#define ODIM   256
#define H1     512
#define AH     128
#define IH     512
#define CDIM   (EDIM + VDIM)   // 512
#define NCHUNK (MKEYS / 128)   // 1024 key tiles
#define NEG_BIG (-1e9f)

// ---------------- scratch (static device globals; no allocation) ----------------
__device__ float g_hidden[BQ * H1];                         // 4 MB
__device__ float g_qn[BQ * KDIM];                           // 1 MB (fp32 normalized query)
__device__ __align__(16) __nv_bfloat16 g_qhi[BQ * KDIM];    // 512 KB
__device__ __align__(16) __nv_bfloat16 g_khi[MKEYS * KDIM]; // 32 MB (bf16 normalized keys)
__device__ float g_invn[MKEYS];                             // 0.5 MB
__device__ float g_pval[BQ * NCHUNK * 2];                   // 16 MB
__device__ int   g_pidx[BQ * NCHUNK * 2];                   // 16 MB
__device__ int   g_topidx[BQ * 3];
__device__ int   g_hitflag[BQ * 3];
__device__ int   g_anyhit[BQ];
__device__ float g_comb[BQ * CDIM];                         // 4 MB
__device__ float g_g1[BQ * IH];                             // 4 MB

// ================= base-ISA PTX helpers (no sm_103a-gated features) =================
__device__ __forceinline__ uint32_t smem_u32(const void* p) {
    uint32_t a;
    asm("{ .reg .u64 t; cvta.to.shared.u64 t, %1; cvt.u32.u64 %0, t; }" : "=r"(a) : "l"(p));
    return a;
}
__device__ __forceinline__ void ldsm4(uint32_t* r, uint32_t addr) {
    asm volatile("ldmatrix.sync.aligned.m8n8.x4.shared.b16 {%0,%1,%2,%3}, [%4];"
                 : "=r"(r[0]), "=r"(r[1]), "=r"(r[2]), "=r"(r[3]) : "r"(addr));
}
__device__ __forceinline__ void mma16816(float* d, const uint32_t* a, const uint32_t* b) {
    asm volatile(
        "mma.sync.aligned.m16n8k16.row.col.f32.bf16.bf16.f32 "
        "{%0,%1,%2,%3}, {%4,%5,%6,%7}, {%8,%9}, {%0,%1,%2,%3};"
        : "+f"(d[0]), "+f"(d[1]), "+f"(d[2]), "+f"(d[3])
        : "r"(a[0]), "r"(a[1]), "r"(a[2]), "r"(a[3]), "r"(b[0]), "r"(b[1]));
}
__device__ __forceinline__ void cp16(uint32_t saddr, const void* gaddr) {
    asm volatile("cp.async.cg.shared.global [%0], [%1], 16;" :: "r"(saddr), "l"(gaddr));
}
#define CP_COMMIT() asm volatile("cp.async.commit_group;" ::: "memory")
#define CP_WAIT0()  asm volatile("cp.async.wait_group 0;" ::: "memory")

// ---------------- K1: hidden = relu(state @ k_w1 + k_b1) ----------------
__global__ void k1_hidden(const float* __restrict__ S, const float* __restrict__ W,
                          const float* __restrict__ b) {
    __shared__ float xs[16][EDIM];
    int r0 = blockIdx.x * 16;
    int tid = threadIdx.x;
    for (int i = tid; i < 16 * EDIM; i += 256) {
        int r = i >> 8, c = i & 255;
        xs[r][c] = S[(r0 + r) * EDIM + c];
    }
    __syncthreads();
    for (int j = tid; j < H1; j += 256) {
        float acc[16];
        float bj = b[j];
#pragma unroll
        for (int r = 0; r < 16; r++) acc[r] = bj;
        for (int k = 0; k < EDIM; k++) {
            float w = W[k * H1 + j];
#pragma unroll
            for (int r = 0; r < 16; r++) acc[r] = fmaf(xs[r][k], w, acc[r]);
        }
#pragma unroll
        for (int r = 0; r < 16; r++) g_hidden[(r0 + r) * H1 + j] = fmaxf(acc[r], 0.f);
    }
}

// ---------------- K2: query = hidden @ k_w2 + k_b2, normalize -> fp32 + bf16 ----------------
__global__ void k2_query(const float* __restrict__ W, const float* __restrict__ b) {
    __shared__ float xs[16][H1];
    __shared__ float qs[16][KDIM];
    __shared__ float sinv[16];
    int r0 = blockIdx.x * 16;
    int tid = threadIdx.x;  // 128 threads
    for (int i = tid; i < 16 * H1; i += 128) {
        int r = i >> 9, c = i & 511;
        xs[r][c] = g_hidden[(r0 + r) * H1 + c];
    }
    __syncthreads();
    int j = tid;
    float acc[16];
    float bj = b[j];
#pragma unroll
    for (int r = 0; r < 16; r++) acc[r] = bj;
    for (int k = 0; k < H1; k++) {
        float w = W[k * KDIM + j];
#pragma unroll
        for (int r = 0; r < 16; r++) acc[r] = fmaf(xs[r][k], w, acc[r]);
    }
#pragma unroll
    for (int r = 0; r < 16; r++) qs[r][j] = acc[r];
    __syncthreads();
    if (tid < 16) {
        float s = 0.f;
        for (int c = 0; c < KDIM; c++) { float v = qs[tid][c]; s += v * v; }
        sinv[tid] = 1.f / fmaxf(sqrtf(s), 1e-8f);
    }
    __syncthreads();
    for (int i = tid; i < 16 * KDIM; i += 128) {
        int r = i >> 7, c = i & 127;
        float x = qs[r][c] * sinv[r];
        g_qn[(size_t)(r0 + r) * KDIM + c] = x;
        g_qhi[(size_t)(r0 + r) * KDIM + c] = __float2bfloat16(x);
    }
}

// ---------------- KC: key inverse norms + normalized bf16 keys ----------------
__global__ void kc_keys(const float* __restrict__ keys) {
    int row = blockIdx.x * 8 + (threadIdx.x >> 5);
    int lane = threadIdx.x & 31;
    float4 v = ((const float4*)keys)[(size_t)row * 32 + lane];
    float s = v.x * v.x + v.y * v.y + v.z * v.z + v.w * v.w;
#pragma unroll
    for (int o = 16; o > 0; o >>= 1) s += __shfl_xor_sync(0xffffffffu, s, o);
    float in = 1.f / fmaxf(sqrtf(s), 1e-8f);
    if (lane == 0) g_invn[row] = in;
    unsigned short hb[4];
    hb[0] = __bfloat16_as_ushort(__float2bfloat16(v.x * in));
    hb[1] = __bfloat16_as_ushort(__float2bfloat16(v.y * in));
    hb[2] = __bfloat16_as_ushort(__float2bfloat16(v.z * in));
    hb[3] = __bfloat16_as_ushort(__float2bfloat16(v.w * in));
    uint2 uh;
    uh.x = (uint32_t)hb[0] | ((uint32_t)hb[1] << 16);
    uh.y = (uint32_t)hb[2] | ((uint32_t)hb[3] << 16);
    ((uint2*)g_khi)[(size_t)row * 32 + lane] = uh;
}

// ---------------- K4: bf16 HMMA GEMM (128x128 tiles) + fused per-tile top-2 ----------------
// smem: A [128][136] bf16 (34816 B), B double buffer 2x[128][136]
#define AROW   136
#define TILEB  (128 * AROW * 2)     // 34816
#define SMEM_K4 (3 * TILEB)         // 104448
#define GX 64                       // CTAs along key dim
#define NT_PER_CTA (NCHUNK / GX)    // 16

__device__ __forceinline__ void load_tile_cp(uint32_t sdst, const __nv_bfloat16* __restrict__ g,
                                             int grow0, int tid) {
#pragma unroll
    for (int i = 0; i < 8; i++) {
        int idx = i * 256 + tid;      // 2048 chunks of 16B
        int r = idx >> 4;             // row 0..127
        int c = idx & 15;             // 16B chunk (16 per row)
        cp16(sdst + r * (AROW * 2) + c * 16, (const void*)(g + (size_t)(grow0 + r) * KDIM + c * 8));
    }
}

__global__ void __launch_bounds__(256) k4_gemm() {
    extern __shared__ char smem[];
    const uint32_t sb = smem_u32(smem);
    const uint32_t sA = sb, sB0 = sb + TILEB, sB1 = sb + 2 * TILEB;
    const int tid = threadIdx.x;
    const int lane = tid & 31, w = tid >> 5;
    const int row0 = blockIdx.y * 128;
    const int m0 = w * 16;

    // lane-fixed ldmatrix addresses
    const uint32_t aAddr = sA + (uint32_t)(((m0 + (lane & 15)) * AROW + ((lane >> 4) & 1) * 8) * 2);
    const uint32_t bLane = (uint32_t)(((((lane & 7) + ((lane >> 4) << 3)) * AROW) + ((lane >> 3) & 1) * 8) * 2);

    // initial loads: A (once) + B tile 0
    load_tile_cp(sA, g_qhi, row0, tid);
    load_tile_cp(sB0, g_khi, blockIdx.x * 128, tid);
    CP_COMMIT();
    CP_WAIT0();
    __syncthreads();

    for (int i = 0; i < NT_PER_CTA; i++) {
        const int kt = i * GX + blockIdx.x;
        const uint32_t sBuf = (i & 1) ? sB1 : sB0;

        // prefetch next B tile
        if (i + 1 < NT_PER_CTA) {
            const int ktn = (i + 1) * GX + blockIdx.x;
            load_tile_cp((i & 1) ? sB0 : sB1, g_khi, ktn * 128, tid);
        }
        CP_COMMIT();

        float acc[16][4];
#pragma unroll
        for (int j = 0; j < 16; j++)
#pragma unroll
            for (int q = 0; q < 4; q++) acc[j][q] = 0.f;

#pragma unroll
        for (int s = 0; s < 8; s++) {
            uint32_t a[4];
            ldsm4(a, aAddr + s * 32);
#pragma unroll
            for (int g = 0; g < 8; g++) {
                uint32_t bfr[4];
                ldsm4(bfr, sBuf + bLane + (uint32_t)(g * 16 * AROW * 2) + s * 32);
                mma16816(acc[2 * g],     a, bfr);
                mma16816(acc[2 * g + 1], a, bfr + 2);
            }
        }

        // ---- epilogue: per-row top-2 over this tile's 128 keys ----
        const int r_lo = lane >> 2, quad = lane & 3;
        float a0v = -FLT_MAX, a1v = -FLT_MAX;   // row m0 + r_lo
        float b0v = -FLT_MAX, b1v = -FLT_MAX;   // row m0 + r_lo + 8
#pragma unroll
        for (int j = 0; j < 16; j++) {
            unsigned cb = (unsigned)(8 * j + 2 * quad);
            float p;
            p = __uint_as_float((__float_as_uint(acc[j][0]) & 0xFFFFFF80u) | cb);
            if (p > a0v) { a1v = a0v; a0v = p; } else if (p > a1v) a1v = p;
            p = __uint_as_float((__float_as_uint(acc[j][1]) & 0xFFFFFF80u) | (cb + 1));
            if (p > a0v) { a1v = a0v; a0v = p; } else if (p > a1v) a1v = p;
            p = __uint_as_float((__float_as_uint(acc[j][2]) & 0xFFFFFF80u) | cb);
            if (p > b0v) { b1v = b0v; b0v = p; } else if (p > b1v) b1v = p;
            p = __uint_as_float((__float_as_uint(acc[j][3]) & 0xFFFFFF80u) | (cb + 1));
            if (p > b0v) { b1v = b0v; b0v = p; } else if (p > b1v) b1v = p;
        }
#pragma unroll
        for (int off = 1; off <= 2; off <<= 1) {
            float u0 = __shfl_xor_sync(0xffffffffu, a0v, off);
            float u1 = __shfl_xor_sync(0xffffffffu, a1v, off);
            if (u0 > a0v) { a1v = fmaxf(a0v, u1); a0v = u0; } else { a1v = fmaxf(a1v, u0); }
            u0 = __shfl_xor_sync(0xffffffffu, b0v, off);
            u1 = __shfl_xor_sync(0xffffffffu, b1v, off);
            if (u0 > b0v) { b1v = fmaxf(b0v, u1); b0v = u0; } else { b1v = fmaxf(b1v, u0); }
        }
        if (quad == 0) {
            int grow = row0 + m0 + r_lo;
            size_t base = ((size_t)grow * NCHUNK + kt) * 2;
            g_pval[base + 0] = a0v; g_pidx[base + 0] = kt * 128 + (int)(__float_as_uint(a0v) & 127u);
            g_pval[base + 1] = a1v; g_pidx[base + 1] = kt * 128 + (int)(__float_as_uint(a1v) & 127u);
            grow += 8;
            base = ((size_t)grow * NCHUNK + kt) * 2;
            g_pval[base + 0] = b0v; g_pidx[base + 0] = kt * 128 + (int)(__float_as_uint(b0v) & 127u);
            g_pval[base + 1] = b1v; g_pidx[base + 1] = kt * 128 + (int)(__float_as_uint(b1v) & 127u);
        }

        CP_WAIT0();
        __syncthreads();
    }
}

// ---------------- K5: merge tile top-2 -> bf16 top-8 -> fp32 rescore -> top-3 ----------------
__device__ __forceinline__ bool better(float v, int i, float V, int I) {
    return (v > V) || (v == V && (unsigned)i < (unsigned)I);
}

__global__ void k5_merge(const float* __restrict__ keys) {
    int row = blockIdx.x;
    int tid = threadIdx.x;  // 128
    __shared__ float sv[128 * 8];
    __shared__ int   si[128 * 8];
    __shared__ float qrow[KDIM];
    __shared__ int   c_idx[8];
    __shared__ float c_val[8];

    qrow[tid] = g_qn[(size_t)row * KDIM + tid];

    float V[8]; int I[8];
#pragma unroll
    for (int t = 0; t < 8; t++) { V[t] = -FLT_MAX; I[t] = 0x7fffffff; }
    for (int e = tid; e < NCHUNK * 2; e += 128) {
        float v = g_pval[(size_t)row * (NCHUNK * 2) + e];
        int id = g_pidx[(size_t)row * (NCHUNK * 2) + e];
        if (better(v, id, V[7], I[7])) {
            V[7] = v; I[7] = id;
#pragma unroll
            for (int t = 7; t >= 1; t--) {
                if (better(V[t], I[t], V[t - 1], I[t - 1])) {
                    float tv = V[t]; V[t] = V[t - 1]; V[t - 1] = tv;
                    int ti = I[t]; I[t] = I[t - 1]; I[t - 1] = ti;
                }
            }
        }
    }
#pragma unroll
    for (int t = 0; t < 8; t++) { sv[tid * 8 + t] = V[t]; si[tid * 8 + t] = I[t]; }
    __syncthreads();

    if (tid == 0) {
        float W8[8]; int J8[8];
#pragma unroll
        for (int t = 0; t < 8; t++) { W8[t] = sv[t]; J8[t] = si[t]; }
        // ensure initial 8 sorted (they are: per-thread lists sorted)
        for (int n = 8; n < 128 * 8; n++) {
            float v = sv[n]; int id = si[n];
            if (better(v, id, W8[7], J8[7])) {
                W8[7] = v; J8[7] = id;
#pragma unroll
                for (int t = 7; t >= 1; t--) {
                    if (better(W8[t], J8[t], W8[t - 1], J8[t - 1])) {
                        float tv = W8[t]; W8[t] = W8[t - 1]; W8[t - 1] = tv;
                        int ti = J8[t]; J8[t] = J8[t - 1]; J8[t - 1] = ti;
                    }
                }
            }
        }
#pragma unroll
        for (int t = 0; t < 8; t++) c_idx[t] = J8[t];
    }
    __syncthreads();

    // exact fp32 rescore of 8 candidates
    {
        int c = tid >> 4, l = tid & 15;
        int idx = c_idx[c];
        float part = 0.f;
#pragma unroll
        for (int jj = 0; jj < 8; jj++) {
            int k = l + jj * 16;
            part += qrow[k] * keys[(size_t)idx * KDIM + k];
        }
#pragma unroll
        for (int off = 8; off; off >>= 1) part += __shfl_xor_sync(0xffffffffu, part, off);
        if (l == 0) c_val[c] = part * g_invn[idx];
    }
    __syncthreads();

    if (tid == 0) {
        // pick top-3 by (exact val desc, idx asc)
        int used = 0;
        int sel[3]; float selv[3];
#pragma unroll
        for (int k = 0; k < 3; k++) {
            float bv = -FLT_MAX; int bi = 0x7fffffff; int bs = -1;
#pragma unroll
            for (int t = 0; t < 8; t++) {
                if (used & (1 << t)) continue;
                if (better(c_val[t], c_idx[t], bv, bi)) { bv = c_val[t]; bi = c_idx[t]; bs = t; }
            }
            used |= (1 << bs);
            sel[k] = bi; selv[k] = bv;
        }
        int h0 = (selv[0] >= 0.f), h1 = (selv[1] >= 0.f), h2 = (selv[2] >= 0.f);
        g_topidx[row * 3 + 0] = sel[0];
        g_topidx[row * 3 + 1] = sel[1];
        g_topidx[row * 3 + 2] = sel[2];
        g_hitflag[row * 3 + 0] = h0;
        g_hitflag[row * 3 + 1] = h1;
        g_hitflag[row * 3 + 2] = h2;
        g_anyhit[row] = h0 | h1 | h2;
    }
}

// ---------------- K6: attention over retrieved memories; build combined ----------------
__global__ void k6_attn(const float* __restrict__ S, const float* __restrict__ values,
                        const float* __restrict__ aw1, const float* __restrict__ ab1,
                        const float* __restrict__ aw2, const float* __restrict__ ab2) {
    __shared__ float xs[EDIM];
    __shared__ float vs[3][VDIM];
    __shared__ float red[3][AH];
    __shared__ float lg[3];
    __shared__ float attn[3];
    __shared__ int sidx[3];
    __shared__ int shit[3];
    int row = blockIdx.x, tid = threadIdx.x;  // 128 threads
    if (tid < 3) { sidx[tid] = g_topidx[row * 3 + tid]; shit[tid] = g_hitflag[row * 3 + tid]; }
    for (int i = tid; i < EDIM; i += AH) xs[i] = S[row * EDIM + i];
    __syncthreads();
    for (int i = tid; i < 3 * VDIM; i += AH) {
        int t = i / VDIM, d = i - t * VDIM;
        vs[t][d] = values[(size_t)sidx[t] * VDIM + d];
    }
    __syncthreads();
    int j = tid;
    float accc = ab1[j];
    for (int k = 0; k < EDIM; k++) accc = fmaf(xs[k], aw1[k * AH + j], accc);
    float w2 = aw2[j];
#pragma unroll
    for (int t = 0; t < 3; t++) {
        float a = accc;
        for (int k = 0; k < VDIM; k++) a = fmaf(vs[t][k], aw1[(EDIM + k) * AH + j], a);
        red[t][j] = tanhf(a) * w2;
    }
    __syncthreads();
    if (tid < 3) {
        float s = ab2[0];
        for (int i = 0; i < AH; i++) s += red[tid][i];
        lg[tid] = shit[tid] ? s : NEG_BIG;
    }
    __syncthreads();
    if (tid == 0) {
        float m = fmaxf(lg[0], fmaxf(lg[1], lg[2]));
        float e0 = expf(lg[0] - m), e1 = expf(lg[1] - m), e2 = expf(lg[2] - m);
        float inv = 1.f / (e0 + e1 + e2);
        attn[0] = e0 * inv; attn[1] = e1 * inv; attn[2] = e2 * inv;
    }
    __syncthreads();
    for (int d = tid; d < VDIM; d += AH) {
        float m = attn[0] * vs[0][d] + attn[1] * vs[1][d] + attn[2] * vs[2][d];
        g_comb[row * CDIM + EDIM + d] = m;
    }
    for (int d = tid; d < EDIM; d += AH) g_comb[row * CDIM + d] = xs[d];
}

// ---------------- K7: g1 = relu(combined @ i_w1 + i_b1) ----------------
__global__ void k7_int1(const float* __restrict__ W, const float* __restrict__ b) {
    __shared__ float xs[16][CDIM];
    int r0 = blockIdx.x * 16, tid = threadIdx.x;  // 256 threads
    for (int i = tid; i < 16 * CDIM; i += 256) {
        int r = i >> 9, c = i & 511;
        xs[r][c] = g_comb[(r0 + r) * CDIM + c];
    }
    __syncthreads();
    for (int j = tid; j < IH; j += 256) {
        float acc[16];
        float bj = b[j];
#pragma unroll
        for (int r = 0; r < 16; r++) acc[r] = bj;
        for (int k = 0; k < CDIM; k++) {
            float w = W[k * IH + j];
#pragma unroll
            for (int r = 0; r < 16; r++) acc[r] = fmaf(xs[r][k], w, acc[r]);
        }
#pragma unroll
        for (int r = 0; r < 16; r++) g_g1[(r0 + r) * IH + j] = fmaxf(acc[r], 0.f);
    }
}

// ---------------- K8: out = g1 @ i_w2 + i_b2 ----------------
__global__ void k8_int2(const float* __restrict__ W, const float* __restrict__ b,
                        float* __restrict__ out) {
    __shared__ float xs[16][IH];
    int r0 = blockIdx.x * 16, tid = threadIdx.x;  // 256 threads
    for (int i = tid; i < 16 * IH; i += 256) {
        int r = i >> 9, c = i & 511;
        xs[r][c] = g_g1[(r0 + r) * IH + c];
    }
    __syncthreads();
    int j = tid;  // ODIM == 256
    float acc[16];
    float bj = b[j];
#pragma unroll
    for (int r = 0; r < 16; r++) acc[r] = bj;
    for (int k = 0; k < IH; k++) {
        float w = W[k * ODIM + j];
#pragma unroll
        for (int r = 0; r < 16; r++) acc[r] = fmaf(xs[r][k], w, acc[r]);
    }
#pragma unroll
    for (int r = 0; r < 16; r++) out[(r0 + r) * ODIM + j] = acc[r];
}

// ---------------- K9: fallback path for rows with no hit (rare/never) ----------------
__global__ void k9_fallback(const float* __restrict__ S,
                            const float* __restrict__ fw1, const float* __restrict__ fb1,
                            const float* __restrict__ fw2, const float* __restrict__ fb2,
                            float* __restrict__ out) {
    int row = blockIdx.x;
    if (g_anyhit[row]) return;
    __shared__ float xs[EDIM];
    __shared__ float h[IH];
    int tid = threadIdx.x;  // 256
    for (int i = tid; i < EDIM; i += 256) xs[i] = S[row * EDIM + i];
    __syncthreads();
    for (int j = tid; j < IH; j += 256) {
        float a = fb1[j];
        for (int k = 0; k < EDIM; k++) a = fmaf(xs[k], fw1[k * IH + j], a);
        h[j] = fmaxf(a, 0.f);
    }
    __syncthreads();
    {
        int j = tid;
        float a = fb2[j];
        for (int k = 0; k < IH; k++) a = fmaf(h[k], fw2[k * ODIM + j], a);
        out[row * ODIM + j] = a;
    }
}

// ---------------- launch ----------------
extern "C" void kernel_launch(void* const* d_in, const int* in_sizes, int n_in,
                              void* d_out, int out_size) {
    const float* S    = (const float*)d_in[0];
    const float* keys = (const float*)d_in[1];
    const float* vals = (const float*)d_in[2];
    const float* kw1  = (const float*)d_in[3];
    const float* kb1  = (const float*)d_in[4];
    const float* kw2  = (const float*)d_in[5];
    const float* kb2  = (const float*)d_in[6];
    const float* aw1  = (const float*)d_in[7];
    const float* ab1  = (const float*)d_in[8];
    const float* aw2  = (const float*)d_in[9];
    const float* ab2  = (const float*)d_in[10];
    const float* iw1  = (const float*)d_in[11];
    const float* ib1  = (const float*)d_in[12];
    const float* iw2  = (const float*)d_in[13];
    const float* ib2  = (const float*)d_in[14];
    const float* fw1  = (const float*)d_in[15];
    const float* fb1  = (const float*)d_in[16];
    const float* fw2  = (const float*)d_in[17];
    const float* fb2  = (const float*)d_in[18];
    float* out = (float*)d_out;

    static int configured = 0;
    if (!configured) {
        cudaFuncSetAttribute(k4_gemm, cudaFuncAttributeMaxDynamicSharedMemorySize, SMEM_K4);
        configured = 1;
    }

    kc_keys<<<MKEYS / 8, 256>>>(keys);
    k1_hidden<<<BQ / 16, 256>>>(S, kw1, kb1);
    k2_query<<<BQ / 16, 128>>>(kw2, kb2);
    k4_gemm<<<dim3(GX, BQ / 128), 256, SMEM_K4>>>();
    k5_merge<<<BQ, 128>>>(keys);
    k6_attn<<<BQ, 128>>>(S, vals, aw1, ab1, aw2, ab2);
    k7_int1<<<BQ / 16, 256>>>(iw1, ib1);
    k8_int2<<<BQ / 16, 256>>>(iw2, ib2, out);
    k9_fallback<<<BQ, 256>>>(S, fw1, fb1, fw2, fb2, out);
}

// round 5
// speedup vs baseline: 4.9324x; 1.2436x over previous
#include <cuda_runtime.h>
#include <cuda_bf16.h>
#include <math.h>
#include <float.h>
#include <stdint.h>

#define BQ     2048
#define MKEYS  131072
#define EDIM   256
#define KDIM   128
#define VDIM   256
#define ODIM   256
#define H1     512
#define AH     128
#define IH     512
#define CDIM   (EDIM + VDIM)   // 512
#define NCH2   2048            // 64-key chunks
#define NEG_BIG (-1e9f)

// ---------------- scratch (static device globals; no allocation) ----------------
__device__ float g_hidden[BQ * H1];                         // 4 MB
__device__ float g_qn[BQ * KDIM];                           // 1 MB
__device__ __align__(16) __nv_bfloat16 g_qhi[BQ * KDIM];    // 512 KB
__device__ __align__(16) __nv_bfloat16 g_khi[MKEYS * KDIM]; // 32 MB
__device__ float g_invn[MKEYS];                             // 0.5 MB
__device__ float g_pval[BQ * NCH2 * 2];                     // 32 MB
__device__ int   g_pidx[BQ * NCH2 * 2];                     // 32 MB
__device__ int   g_topidx[BQ * 3];
__device__ int   g_hitflag[BQ * 3];
__device__ int   g_anyhit[BQ];
__device__ float g_comb[BQ * CDIM];                         // 4 MB
__device__ float g_g1[BQ * IH];                             // 4 MB

// ================= helpers =================
typedef unsigned long long ull;
__device__ __forceinline__ ull pack2(float x, float y) {
    ull r; asm("mov.b64 %0, {%1, %2};" : "=l"(r) : "f"(x), "f"(y)); return r;
}
__device__ __forceinline__ void fma2(ull& d, ull a, ull b) {
    asm("fma.rn.f32x2 %0, %1, %2, %0;" : "+l"(d) : "l"(a), "l"(b));
}
__device__ __forceinline__ float2 unpack2(ull v) {
    float2 f; asm("mov.b64 {%0, %1}, %2;" : "=f"(f.x), "=f"(f.y) : "l"(v)); return f;
}
__device__ __forceinline__ uint32_t smem_u32(const void* p) {
    uint32_t a;
    asm("{ .reg .u64 t; cvta.to.shared.u64 t, %1; cvt.u32.u64 %0, t; }" : "=r"(a) : "l"(p));
    return a;
}
__device__ __forceinline__ void ldsm4(uint32_t* r, uint32_t addr) {
    asm volatile("ldmatrix.sync.aligned.m8n8.x4.shared.b16 {%0,%1,%2,%3}, [%4];"
                 : "=r"(r[0]), "=r"(r[1]), "=r"(r[2]), "=r"(r[3]) : "r"(addr));
}
__device__ __forceinline__ void mma16816(float* d, const uint32_t* a, const uint32_t* b) {
    asm volatile(
        "mma.sync.aligned.m16n8k16.row.col.f32.bf16.bf16.f32 "
        "{%0,%1,%2,%3}, {%4,%5,%6,%7}, {%8,%9}, {%0,%1,%2,%3};"
        : "+f"(d[0]), "+f"(d[1]), "+f"(d[2]), "+f"(d[3])
        : "r"(a[0]), "r"(a[1]), "r"(a[2]), "r"(a[3]), "r"(b[0]), "r"(b[1]));
}
__device__ __forceinline__ void cp16(uint32_t saddr, const void* gaddr) {
    asm volatile("cp.async.cg.shared.global [%0], [%1], 16;" :: "r"(saddr), "l"(gaddr));
}
#define CP_COMMIT() asm volatile("cp.async.commit_group;" ::: "memory")
#define CP_WAIT0()  asm volatile("cp.async.wait_group 0;" ::: "memory")

// ---------------- K1: hidden = relu(state @ k_w1 + k_b1)  (f32x2) ----------------
__global__ void __launch_bounds__(256) k1_hidden(const float* __restrict__ S,
                                                 const float* __restrict__ W,
                                                 const float* __restrict__ b) {
    __shared__ float4 xs4[EDIM][5];   // rows packed 4 per float4, padded
    int r0 = blockIdx.x * 16;
    int tid = threadIdx.x;
    int j = blockIdx.y * 256 + tid;
    for (int i = tid; i < 16 * EDIM; i += 256) {
        int r = i >> 8, c = i & 255;
        ((float*)&xs4[c][0])[r] = S[(r0 + r) * EDIM + c];
    }
    __syncthreads();
    float bj = b[j];
    ull acc[8];
#pragma unroll
    for (int p = 0; p < 8; p++) acc[p] = pack2(bj, bj);
    for (int k = 0; k < EDIM; k += 8) {
        float w[8];
#pragma unroll
        for (int u = 0; u < 8; u++) w[u] = W[(k + u) * H1 + j];
#pragma unroll
        for (int u = 0; u < 8; u++) {
            ull wp = pack2(w[u], w[u]);
#pragma unroll
            for (int p4 = 0; p4 < 4; p4++) {
                float4 xv = xs4[k + u][p4];
                fma2(acc[2 * p4],     pack2(xv.x, xv.y), wp);
                fma2(acc[2 * p4 + 1], pack2(xv.z, xv.w), wp);
            }
        }
    }
#pragma unroll
    for (int p = 0; p < 8; p++) {
        float2 f = unpack2(acc[p]);
        g_hidden[(size_t)(r0 + 2 * p) * H1 + j]     = fmaxf(f.x, 0.f);
        g_hidden[(size_t)(r0 + 2 * p + 1) * H1 + j] = fmaxf(f.y, 0.f);
    }
}

// ---------------- K2: query GEMM + normalize -> fp32 + bf16 (f32x2) ----------------
__global__ void __launch_bounds__(128) k2_query(const float* __restrict__ W,
                                                const float* __restrict__ b) {
    __shared__ char sbuf[H1 * 5 * 16];   // xs4 then reused as qs
    __shared__ float sinv[16];
    float4 (*xs4)[5] = (float4(*)[5])sbuf;
    float* qs = (float*)sbuf;            // [16][KDIM] overlay (8 KB)
    int r0 = blockIdx.x * 16;
    int tid = threadIdx.x;               // 128, j = tid
    for (int i = tid; i < 16 * H1; i += 128) {
        int r = i >> 9, c = i & 511;
        ((float*)&xs4[c][0])[r] = g_hidden[(size_t)(r0 + r) * H1 + c];
    }
    __syncthreads();
    float bj = b[tid];
    ull acc[8];
#pragma unroll
    for (int p = 0; p < 8; p++) acc[p] = pack2(bj, bj);
    for (int k = 0; k < H1; k += 8) {
        float w[8];
#pragma unroll
        for (int u = 0; u < 8; u++) w[u] = W[(k + u) * KDIM + tid];
#pragma unroll
        for (int u = 0; u < 8; u++) {
            ull wp = pack2(w[u], w[u]);
#pragma unroll
            for (int p4 = 0; p4 < 4; p4++) {
                float4 xv = xs4[k + u][p4];
                fma2(acc[2 * p4],     pack2(xv.x, xv.y), wp);
                fma2(acc[2 * p4 + 1], pack2(xv.z, xv.w), wp);
            }
        }
    }
    __syncthreads();   // done with xs4; reuse as qs
#pragma unroll
    for (int p = 0; p < 8; p++) {
        float2 f = unpack2(acc[p]);
        qs[(2 * p) * KDIM + tid]     = f.x;
        qs[(2 * p + 1) * KDIM + tid] = f.y;
    }
    __syncthreads();
    if (tid < 16) {
        float s = 0.f;
        for (int c = 0; c < KDIM; c++) { float v = qs[tid * KDIM + c]; s += v * v; }
        sinv[tid] = 1.f / fmaxf(sqrtf(s), 1e-8f);
    }
    __syncthreads();
    for (int i = tid; i < 16 * KDIM; i += 128) {
        int r = i >> 7, c = i & 127;
        float x = qs[r * KDIM + c] * sinv[r];
        g_qn[(size_t)(r0 + r) * KDIM + c] = x;
        g_qhi[(size_t)(r0 + r) * KDIM + c] = __float2bfloat16(x);
    }
}

// ---------------- KC: key inverse norms + normalized bf16 keys ----------------
__global__ void kc_keys(const float* __restrict__ keys) {
    int row = blockIdx.x * 8 + (threadIdx.x >> 5);
    int lane = threadIdx.x & 31;
    float4 v = ((const float4*)keys)[(size_t)row * 32 + lane];
    float s = v.x * v.x + v.y * v.y + v.z * v.z + v.w * v.w;
#pragma unroll
    for (int o = 16; o > 0; o >>= 1) s += __shfl_xor_sync(0xffffffffu, s, o);
    float in = 1.f / fmaxf(sqrtf(s), 1e-8f);
    if (lane == 0) g_invn[row] = in;
    unsigned short hb[4];
    hb[0] = __bfloat16_as_ushort(__float2bfloat16(v.x * in));
    hb[1] = __bfloat16_as_ushort(__float2bfloat16(v.y * in));
    hb[2] = __bfloat16_as_ushort(__float2bfloat16(v.z * in));
    hb[3] = __bfloat16_as_ushort(__float2bfloat16(v.w * in));
    uint2 uh;
    uh.x = (uint32_t)hb[0] | ((uint32_t)hb[1] << 16);
    uh.y = (uint32_t)hb[2] | ((uint32_t)hb[3] << 16);
    ((uint2*)g_khi)[(size_t)row * 32 + lane] = uh;
}

// ---------------- K4: bf16 HMMA GEMM (128x128 tile, warp=32Mx64N) + fused top-2 ----------------
#define AROW   136
#define TILEB  (128 * AROW * 2)     // 34816
#define SMEM_K4 (3 * TILEB)         // 104448
#define GX 64
#define NT_PER_CTA (1024 / GX)      // 16 tiles of 128 keys per CTA

__device__ __forceinline__ void load_tile_cp(uint32_t sdst, const __nv_bfloat16* __restrict__ g,
                                             int grow0, int tid) {
#pragma unroll
    for (int i = 0; i < 8; i++) {
        int idx = i * 256 + tid;
        int r = idx >> 4, c = idx & 15;
        cp16(sdst + r * (AROW * 2) + c * 16, (const void*)(g + (size_t)(grow0 + r) * KDIM + c * 8));
    }
}

__global__ void __launch_bounds__(256, 2) k4_gemm() {
    extern __shared__ char smem[];
    const uint32_t sb = smem_u32(smem);
    const uint32_t sA = sb, sB0 = sb + TILEB, sB1 = sb + 2 * TILEB;
    const int tid = threadIdx.x;
    const int lane = tid & 31, w = tid >> 5;
    const int wm = w & 3, wn = w >> 2;       // warp grid 4M x 2N
    const int row0 = blockIdx.y * 128;
    const int m0 = wm * 32;

    uint32_t aAddr[2];
#pragma unroll
    for (int f = 0; f < 2; f++)
        aAddr[f] = sA + (uint32_t)(((m0 + f * 16 + (lane & 15)) * AROW + ((lane >> 4) & 1) * 8) * 2);
    const uint32_t bLane = (uint32_t)(((((lane & 7) + ((lane >> 4) << 3)) * AROW) + ((lane >> 3) & 1) * 8) * 2);

    load_tile_cp(sA, g_qhi, row0, tid);
    load_tile_cp(sB0, g_khi, blockIdx.x * 128, tid);
    CP_COMMIT();
    CP_WAIT0();
    __syncthreads();

    for (int i = 0; i < NT_PER_CTA; i++) {
        const int kt = i * GX + blockIdx.x;
        const uint32_t sBuf = (i & 1) ? sB1 : sB0;

        if (i + 1 < NT_PER_CTA) {
            const int ktn = (i + 1) * GX + blockIdx.x;
            load_tile_cp((i & 1) ? sB0 : sB1, g_khi, ktn * 128, tid);
        }
        CP_COMMIT();

        float acc[2][8][4];
#pragma unroll
        for (int f = 0; f < 2; f++)
#pragma unroll
            for (int j8 = 0; j8 < 8; j8++)
#pragma unroll
                for (int q = 0; q < 4; q++) acc[f][j8][q] = 0.f;

#pragma unroll
        for (int s = 0; s < 8; s++) {
            uint32_t a0[4], a1[4];
            ldsm4(a0, aAddr[0] + s * 32);
            ldsm4(a1, aAddr[1] + s * 32);
#pragma unroll
            for (int g = 0; g < 4; g++) {
                uint32_t bf[4];
                ldsm4(bf, sBuf + bLane + (uint32_t)(((wn * 4 + g) * 16) * (AROW * 2)) + s * 32);
                mma16816(acc[0][2 * g],     a0, bf);
                mma16816(acc[0][2 * g + 1], a0, bf + 2);
                mma16816(acc[1][2 * g],     a1, bf);
                mma16816(acc[1][2 * g + 1], a1, bf + 2);
            }
        }

        // ---- epilogue: per-lane branchless top-2 per row (4 rows/lane), col packed in mantissa ----
        float v0[4], v1[4];
#pragma unroll
        for (int r = 0; r < 4; r++) { v0[r] = -FLT_MAX; v1[r] = -FLT_MAX; }
        const unsigned qb = (lane & 3) * 2;
#pragma unroll
        for (int f = 0; f < 2; f++)
#pragma unroll
            for (int j8 = 0; j8 < 8; j8++)
#pragma unroll
                for (int q = 0; q < 4; q++) {
                    int ridx = f * 2 + (q >> 1);
                    unsigned cloc = (unsigned)(j8 * 8) + qb + (q & 1);
                    float p = __uint_as_float((__float_as_uint(acc[f][j8][q]) & 0xFFFFFFC0u) | cloc);
                    float mx = fmaxf(v0[ridx], p);
                    v1[ridx] = fmaxf(v1[ridx], fminf(v0[ridx], p));
                    v0[ridx] = mx;
                }
#pragma unroll
        for (int off = 1; off <= 2; off <<= 1) {
#pragma unroll
            for (int r = 0; r < 4; r++) {
                float u0 = __shfl_xor_sync(0xffffffffu, v0[r], off);
                float u1 = __shfl_xor_sync(0xffffffffu, v1[r], off);
                v1[r] = fmaxf(fmaxf(v1[r], u1), fminf(v0[r], u0));
                v0[r] = fmaxf(v0[r], u0);
            }
        }
        if ((lane & 3) == 0) {
            const int r_lo = lane >> 2;
            const int c2 = kt * 2 + wn;
            const int cbase = kt * 128 + wn * 64;
#pragma unroll
            for (int r = 0; r < 4; r++) {
                int f = r >> 1, half = r & 1;
                int grow = row0 + m0 + f * 16 + r_lo + half * 8;
                size_t base = ((size_t)grow * NCH2 + c2) * 2;
                g_pval[base + 0] = v0[r];
                g_pidx[base + 0] = cbase + (int)(__float_as_uint(v0[r]) & 63u);
                g_pval[base + 1] = v1[r];
                g_pidx[base + 1] = cbase + (int)(__float_as_uint(v1[r]) & 63u);
            }
        }

        CP_WAIT0();
        __syncthreads();
    }
}

// ---------------- K5: merge chunk top-2 -> bf16 top-8 -> fp32 rescore -> top-3 ----------------
__device__ __forceinline__ bool better(float v, int i, float V, int I) {
    return (v > V) || (v == V && (unsigned)i < (unsigned)I);
}

__global__ void k5_merge(const float* __restrict__ keys) {
    int row = blockIdx.x;
    int tid = threadIdx.x;  // 128
    __shared__ float sv[128 * 8];
    __shared__ int   si[128 * 8];
    __shared__ float qrow[KDIM];
    __shared__ int   c_idx[8];
    __shared__ float c_val[8];

    qrow[tid] = g_qn[(size_t)row * KDIM + tid];

    float V[8]; int I[8];
#pragma unroll
    for (int t = 0; t < 8; t++) { V[t] = -FLT_MAX; I[t] = 0x7fffffff; }
    for (int e = tid; e < NCH2 * 2; e += 128) {
        float v = g_pval[(size_t)row * (NCH2 * 2) + e];
        int id = g_pidx[(size_t)row * (NCH2 * 2) + e];
        if (better(v, id, V[7], I[7])) {
            V[7] = v; I[7] = id;
#pragma unroll
            for (int t = 7; t >= 1; t--) {
                if (better(V[t], I[t], V[t - 1], I[t - 1])) {
                    float tv = V[t]; V[t] = V[t - 1]; V[t - 1] = tv;
                    int ti = I[t]; I[t] = I[t - 1]; I[t - 1] = ti;
                }
            }
        }
    }
#pragma unroll
    for (int t = 0; t < 8; t++) { sv[tid * 8 + t] = V[t]; si[tid * 8 + t] = I[t]; }
    __syncthreads();

    if (tid == 0) {
        float W8[8]; int J8[8];
#pragma unroll
        for (int t = 0; t < 8; t++) { W8[t] = sv[t]; J8[t] = si[t]; }
        for (int n = 8; n < 128 * 8; n++) {
            float v = sv[n]; int id = si[n];
            if (better(v, id, W8[7], J8[7])) {
                W8[7] = v; J8[7] = id;
#pragma unroll
                for (int t = 7; t >= 1; t--) {
                    if (better(W8[t], J8[t], W8[t - 1], J8[t - 1])) {
                        float tv = W8[t]; W8[t] = W8[t - 1]; W8[t - 1] = tv;
                        int ti = J8[t]; J8[t] = J8[t - 1]; J8[t - 1] = ti;
                    }
                }
            }
        }
#pragma unroll
        for (int t = 0; t < 8; t++) c_idx[t] = J8[t];
    }
    __syncthreads();

    // exact fp32 rescore of 8 candidates
    {
        int c = tid >> 4, l = tid & 15;
        int idx = c_idx[c];
        float part = 0.f;
#pragma unroll
        for (int jj = 0; jj < 8; jj++) {
            int k = l + jj * 16;
            part += qrow[k] * keys[(size_t)idx * KDIM + k];
        }
#pragma unroll
        for (int off = 8; off; off >>= 1) part += __shfl_xor_sync(0xffffffffu, part, off);
        if (l == 0) c_val[c] = part * g_invn[idx];
    }
    __syncthreads();

    if (tid == 0) {
        int used = 0;
        int sel[3]; float selv[3];
#pragma unroll
        for (int k = 0; k < 3; k++) {
            float bv = -FLT_MAX; int bi = 0x7fffffff; int bs = -1;
#pragma unroll
            for (int t = 0; t < 8; t++) {
                if (used & (1 << t)) continue;
                if (better(c_val[t], c_idx[t], bv, bi)) { bv = c_val[t]; bi = c_idx[t]; bs = t; }
            }
            used |= (1 << bs);
            sel[k] = bi; selv[k] = bv;
        }
        int h0 = (selv[0] >= 0.f), h1 = (selv[1] >= 0.f), h2 = (selv[2] >= 0.f);
        g_topidx[row * 3 + 0] = sel[0];
        g_topidx[row * 3 + 1] = sel[1];
        g_topidx[row * 3 + 2] = sel[2];
        g_hitflag[row * 3 + 0] = h0;
        g_hitflag[row * 3 + 1] = h1;
        g_hitflag[row * 3 + 2] = h2;
        g_anyhit[row] = h0 | h1 | h2;
    }
}

// ---------------- K6: attention over retrieved memories; build combined ----------------
__global__ void k6_attn(const float* __restrict__ S, const float* __restrict__ values,
                        const float* __restrict__ aw1, const float* __restrict__ ab1,
                        const float* __restrict__ aw2, const float* __restrict__ ab2) {
    __shared__ float xs[EDIM];
    __shared__ float vs[3][VDIM];
    __shared__ float red[3][AH];
    __shared__ float lg[3];
    __shared__ float attn[3];
    __shared__ int sidx[3];
    __shared__ int shit[3];
    int row = blockIdx.x, tid = threadIdx.x;  // 128 threads
    if (tid < 3) { sidx[tid] = g_topidx[row * 3 + tid]; shit[tid] = g_hitflag[row * 3 + tid]; }
    for (int i = tid; i < EDIM; i += AH) xs[i] = S[row * EDIM + i];
    __syncthreads();
    for (int i = tid; i < 3 * VDIM; i += AH) {
        int t = i / VDIM, d = i - t * VDIM;
        vs[t][d] = values[(size_t)sidx[t] * VDIM + d];
    }
    __syncthreads();
    int j = tid;
    float accc = ab1[j];
    for (int k = 0; k < EDIM; k++) accc = fmaf(xs[k], aw1[k * AH + j], accc);
    float w2 = aw2[j];
#pragma unroll
    for (int t = 0; t < 3; t++) {
        float a = accc;
        for (int k = 0; k < VDIM; k++) a = fmaf(vs[t][k], aw1[(EDIM + k) * AH + j], a);
        red[t][j] = tanhf(a) * w2;
    }
    __syncthreads();
    if (tid < 3) {
        float s = ab2[0];
        for (int i = 0; i < AH; i++) s += red[tid][i];
        lg[tid] = shit[tid] ? s : NEG_BIG;
    }
    __syncthreads();
    if (tid == 0) {
        float m = fmaxf(lg[0], fmaxf(lg[1], lg[2]));
        float e0 = expf(lg[0] - m), e1 = expf(lg[1] - m), e2 = expf(lg[2] - m);
        float inv = 1.f / (e0 + e1 + e2);
        attn[0] = e0 * inv; attn[1] = e1 * inv; attn[2] = e2 * inv;
    }
    __syncthreads();
    for (int d = tid; d < VDIM; d += AH) {
        float m = attn[0] * vs[0][d] + attn[1] * vs[1][d] + attn[2] * vs[2][d];
        g_comb[row * CDIM + EDIM + d] = m;
    }
    for (int d = tid; d < EDIM; d += AH) g_comb[row * CDIM + d] = xs[d];
}

// ---------------- K7: g1 = relu(combined @ i_w1 + i_b1)  (f32x2) ----------------
__global__ void __launch_bounds__(256) k7_int1(const float* __restrict__ W,
                                               const float* __restrict__ b) {
    __shared__ float4 xs4[CDIM][5];   // 40 KB
    int r0 = blockIdx.x * 16;
    int tid = threadIdx.x;
    int j = blockIdx.y * 256 + tid;
    for (int i = tid; i < 16 * CDIM; i += 256) {
        int r = i >> 9, c = i & 511;
        ((float*)&xs4[c][0])[r] = g_comb[(size_t)(r0 + r) * CDIM + c];
    }
    __syncthreads();
    float bj = b[j];
    ull acc[8];
#pragma unroll
    for (int p = 0; p < 8; p++) acc[p] = pack2(bj, bj);
    for (int k = 0; k < CDIM; k += 8) {
        float w[8];
#pragma unroll
        for (int u = 0; u < 8; u++) w[u] = W[(k + u) * IH + j];
#pragma unroll
        for (int u = 0; u < 8; u++) {
            ull wp = pack2(w[u], w[u]);
#pragma unroll
            for (int p4 = 0; p4 < 4; p4++) {
                float4 xv = xs4[k + u][p4];
                fma2(acc[2 * p4],     pack2(xv.x, xv.y), wp);
                fma2(acc[2 * p4 + 1], pack2(xv.z, xv.w), wp);
            }
        }
    }
#pragma unroll
    for (int p = 0; p < 8; p++) {
        float2 f = unpack2(acc[p]);
        g_g1[(size_t)(r0 + 2 * p) * IH + j]     = fmaxf(f.x, 0.f);
        g_g1[(size_t)(r0 + 2 * p + 1) * IH + j] = fmaxf(f.y, 0.f);
    }
}

// ---------------- K8: out = g1 @ i_w2 + i_b2  (f32x2) ----------------
__global__ void __launch_bounds__(256) k8_int2(const float* __restrict__ W,
                                               const float* __restrict__ b,
                                               float* __restrict__ out) {
    __shared__ float4 xs4[IH][5];   // 40 KB
    int r0 = blockIdx.x * 16;
    int tid = threadIdx.x;          // j = tid, ODIM == 256
    for (int i = tid; i < 16 * IH; i += 256) {
        int r = i >> 9, c = i & 511;
        ((float*)&xs4[c][0])[r] = g_g1[(size_t)(r0 + r) * IH + c];
    }
    __syncthreads();
    float bj = b[tid];
    ull acc[8];
#pragma unroll
    for (int p = 0; p < 8; p++) acc[p] = pack2(bj, bj);
    for (int k = 0; k < IH; k += 8) {
        float w[8];
#pragma unroll
        for (int u = 0; u < 8; u++) w[u] = W[(k + u) * ODIM + tid];
#pragma unroll
        for (int u = 0; u < 8; u++) {
            ull wp = pack2(w[u], w[u]);
#pragma unroll
            for (int p4 = 0; p4 < 4; p4++) {
                float4 xv = xs4[k + u][p4];
                fma2(acc[2 * p4],     pack2(xv.x, xv.y), wp);
                fma2(acc[2 * p4 + 1], pack2(xv.z, xv.w), wp);
            }
        }
    }
#pragma unroll
    for (int p = 0; p < 8; p++) {
        float2 f = unpack2(acc[p]);
        out[(size_t)(r0 + 2 * p) * ODIM + tid]     = f.x;
        out[(size_t)(r0 + 2 * p + 1) * ODIM + tid] = f.y;
    }
}

// ---------------- K9: fallback path for rows with no hit (rare/never) ----------------
__global__ void k9_fallback(const float* __restrict__ S,
                            const float* __restrict__ fw1, const float* __restrict__ fb1,
                            const float* __restrict__ fw2, const float* __restrict__ fb2,
                            float* __restrict__ out) {
    int row = blockIdx.x;
    if (g_anyhit[row]) return;
    __shared__ float xs[EDIM];
    __shared__ float h[IH];
    int tid = threadIdx.x;  // 256
    for (int i = tid; i < EDIM; i += 256) xs[i] = S[row * EDIM + i];
    __syncthreads();
    for (int j = tid; j < IH; j += 256) {
        float a = fb1[j];
        for (int k = 0; k < EDIM; k++) a = fmaf(xs[k], fw1[k * IH + j], a);
        h[j] = fmaxf(a, 0.f);
    }
    __syncthreads();
    {
        int j = tid;
        float a = fb2[j];
        for (int k = 0; k < IH; k++) a = fmaf(h[k], fw2[k * ODIM + j], a);
        out[row * ODIM + j] = a;
    }
}

// ---------------- launch ----------------
extern "C" void kernel_launch(void* const* d_in, const int* in_sizes, int n_in,
                              void* d_out, int out_size) {
    const float* S    = (const float*)d_in[0];
    const float* keys = (const float*)d_in[1];
    const float* vals = (const float*)d_in[2];
    const float* kw1  = (const float*)d_in[3];
    const float* kb1  = (const float*)d_in[4];
    const float* kw2  = (const float*)d_in[5];
    const float* kb2  = (const float*)d_in[6];
    const float* aw1  = (const float*)d_in[7];
    const float* ab1  = (const float*)d_in[8];
    const float* aw2  = (const float*)d_in[9];
    const float* ab2  = (const float*)d_in[10];
    const float* iw1  = (const float*)d_in[11];
    const float* ib1  = (const float*)d_in[12];
    const float* iw2  = (const float*)d_in[13];
    const float* ib2  = (const float*)d_in[14];
    const float* fw1  = (const float*)d_in[15];
    const float* fb1  = (const float*)d_in[16];
    const float* fw2  = (const float*)d_in[17];
    const float* fb2  = (const float*)d_in[18];
    float* out = (float*)d_out;

    static int configured = 0;
    if (!configured) {
        cudaFuncSetAttribute(k4_gemm, cudaFuncAttributeMaxDynamicSharedMemorySize, SMEM_K4);
        configured = 1;
    }

    kc_keys<<<MKEYS / 8, 256>>>(keys);
    k1_hidden<<<dim3(BQ / 16, 2), 256>>>(S, kw1, kb1);
    k2_query<<<BQ / 16, 128>>>(kw2, kb2);
    k4_gemm<<<dim3(GX, BQ / 128), 256, SMEM_K4>>>();
    k5_merge<<<BQ, 128>>>(keys);
    k6_attn<<<BQ, 128>>>(S, vals, aw1, ab1, aw2, ab2);
    k7_int1<<<dim3(BQ / 16, 2), 256>>>(iw1, ib1);
    k8_int2<<<BQ / 16, 256>>>(iw2, ib2, out);
    k9_fallback<<<BQ, 256>>>(S, fw1, fb1, fw2, fb2, out);
}